// round 10
// baseline (speedup 1.0000x reference)
#include <cuda_runtime.h>

#define EPS  1e-6f
#define TPB  128
#define S7   7             // float4 stride per batch in smem (pad: 6 data + 1)
#define MAXG 8192

// Scratch (no device allocation allowed). Zero-initialized at module load.
// g_ticket self-resets via atomicInc wrap -> deterministic across graph replays.
__device__ float        g_psum[MAXG];
__device__ float        g_pcnt[MAXG];
__device__ unsigned int g_ticket;

__global__ void __launch_bounds__(TPB, 8) gsc_fused(
    const float* __restrict__ pred, const float* __restrict__ gt,
    float* __restrict__ out, int B, int nTiles)
{
    __shared__ float4 sp4[TPB * S7];
    __shared__ float4 sg4[TPB * S7];
    __shared__ float  swsum[4];
    __shared__ float  swcnt[4];
    __shared__ int    s_last;

    const int tid = threadIdx.x;
    float accL = 0.f, accC = 0.f;

    const float4* p4 = reinterpret_cast<const float4*>(pred);
    const float4* g4 = reinterpret_cast<const float4*>(gt);

    for (int tile = blockIdx.x; tile < nTiles; tile += gridDim.x) {
        const int  base  = tile * TPB;
        const int  nB    = min(TPB, B - base);
        const int  n4    = nB * 6;
        const long gbase = (long)base * 6;

        // ---- stage: coalesced LDG.128 -> STS.128 (padded batch stride S7) ----
#pragma unroll
        for (int i = 0; i < 6; ++i) {
            int idx = i * TPB + tid;
            float4 t = make_float4(0.f, 0.f, 0.f, 0.f);
            float4 u = make_float4(0.f, 0.f, 0.f, 0.f);
            if (idx < n4) { t = p4[gbase + idx]; u = g4[gbase + idx]; }
            int r = idx / 6, w = idx - r * 6;
            sp4[r * S7 + w] = t;
            sg4[r * S7 + w] = u;
        }
        __syncthreads();

        // ---- gather this thread's batch: 6+6 LDS.128, conflict-free ----
        float pk[24], gk[24];
#pragma unroll
        for (int w = 0; w < 6; ++w) {
            float4 t = sp4[tid * S7 + w];
            pk[4*w+0] = t.x; pk[4*w+1] = t.y; pk[4*w+2] = t.z; pk[4*w+3] = t.w;
            float4 u = sg4[tid * S7 + w];
            gk[4*w+0] = u.x; gk[4*w+1] = u.y; gk[4*w+2] = u.z; gk[4*w+3] = u.w;
        }

        // ---- stable "first 4 visible" select, fully unrolled (no spills) ----
        float px[4] = {0,0,0,0}, py[4] = {0,0,0,0};
        float gx[4] = {0,0,0,0}, gy[4] = {0,0,0,0};
        int nv = 0;
#pragma unroll
        for (int k = 0; k < 8; ++k) {
            bool vis = (pk[3*k+2] > 0.5f) && (gk[3*k+2] > 0.5f);
#pragma unroll
            for (int s = 0; s < 4; ++s) {
                if (vis && nv == s) {
                    px[s] = pk[3*k+0]; py[s] = pk[3*k+1];
                    gx[s] = gk[3*k+0]; gy[s] = gk[3*k+1];
                }
            }
            nv += vis ? 1 : 0;
        }
        bool valid = (tid < nB) && (nv >= 4);

        // ---- L_shape ----
        float d31x = px[2]-px[0], d31y = py[2]-py[0];
        float d42x = px[3]-px[1], d42y = py[3]-py[1];
        float e31x = gx[2]-gx[0], e31y = gy[2]-gy[0];
        float e42x = gx[3]-gx[1], e42y = gy[3]-gy[1];
        float pcr = __fdividef(sqrtf(d31x*d31x + d31y*d31y),
                               sqrtf(d42x*d42x + d42y*d42y) + EPS);
        float gcr = __fdividef(sqrtf(e31x*e31x + e31y*e31y),
                               sqrtf(e42x*e42x + e42y*e42y) + EPS);
        float L_shape = fabsf(pcr - gcr);

        // ---- L_edge ----
        float v12x = px[1]-px[0], v12y = py[1]-py[0];
        float v23x = px[2]-px[1], v23y = py[2]-py[1];
        float v34x = px[3]-px[2], v34y = py[3]-py[2];
        float v41x = px[0]-px[3], v41y = py[0]-py[3];
        float l12 = sqrtf(v12x*v12x + v12y*v12y);
        float l23 = sqrtf(v23x*v23x + v23y*v23y);
        float l34 = sqrtf(v34x*v34x + v34y*v34y);
        float l41 = sqrtf(v41x*v41x + v41y*v41y);
        float par1 = __fdividef(fabsf(l12 - l34), l12 + l34 + EPS);
        float par2 = __fdividef(fabsf(l23 - l41), l23 + l41 + EPS);
        float dot1 = fabsf(__fdividef(v12x*v41x + v12y*v41y, l12*l41 + EPS));
        float dot2 = fabsf(__fdividef(v12x*v23x + v12y*v23y, l12*l23 + EPS));
        float dot3 = fabsf(__fdividef(v23x*v34x + v23y*v34y, l23*l34 + EPS));
        float dot4 = fabsf(__fdividef(v34x*v41x + v34y*v41y, l34*l41 + EPS));
        float L_edge = 0.5f*(par1 + par2) + 0.25f*(dot1 + dot2 + dot3 + dot4);

        // ---- L_pos ----
        float dist = 0.f;
#pragma unroll
        for (int i = 0; i < 4; ++i) {
            float dx = px[i]-gx[i], dy = py[i]-gy[i];
            dist += sqrtf(dx*dx + dy*dy);
        }
        dist *= 0.25f;

        float d41x = px[3]-px[0], d41y = py[3]-py[0];
        float parea = 0.5f * (fabsf(v12x*d31y - v12y*d31x) +
                              fabsf(d31x*d41y - d31y*d41x));
        float w12x = gx[1]-gx[0], w12y = gy[1]-gy[0];
        float e41x = gx[3]-gx[0], e41y = gy[3]-gy[0];
        float garea = 0.5f * (fabsf(w12x*e31y - w12y*e31x) +
                              fabsf(e31x*e41y - e31y*e41x));
        float area_ratio = __fdividef(fabsf(parea - garea), garea + EPS);

        float dmx = 0.25f*((px[0]-gx[0]) + (px[1]-gx[1]) + (px[2]-gx[2]) + (px[3]-gx[3]));
        float dmy = 0.25f*((py[0]-gy[0]) + (py[1]-gy[1]) + (py[2]-gy[2]) + (py[3]-gy[3]));
        float rel = 0.f;
#pragma unroll
        for (int i = 0; i < 4; ++i) {
            float dx = (px[i]-gx[i]) - dmx;
            float dy = (py[i]-gy[i]) - dmy;
            rel += sqrtf(dx*dx + dy*dy);
        }
        rel *= 0.25f;

        float L_pos = 0.4f*dist + 0.3f*area_ratio + 0.3f*rel;
        float L     = 0.4f*L_shape + 0.3f*L_edge + 0.3f*L_pos;

        accL += valid ? L   : 0.f;
        accC += valid ? 1.f : 0.f;

        __syncthreads();   // protect SMEM before next iteration's staging
    }

    // ---- block reduction ----
    int lane = tid & 31, wid = tid >> 5;
#pragma unroll
    for (int off = 16; off > 0; off >>= 1) {
        accL += __shfl_down_sync(0xffffffffu, accL, off);
        accC += __shfl_down_sync(0xffffffffu, accC, off);
    }
    if (lane == 0) { swsum[wid] = accL; swcnt[wid] = accC; }
    __syncthreads();
    if (tid == 0) {
        float bs = swsum[0] + swsum[1] + swsum[2] + swsum[3];
        float bc = swcnt[0] + swcnt[1] + swcnt[2] + swcnt[3];
        g_psum[blockIdx.x] = bs;
        g_pcnt[blockIdx.x] = bc;
        __threadfence();
        unsigned int t = atomicInc(&g_ticket, gridDim.x - 1); // wraps to 0 -> replay-safe
        s_last = (t == gridDim.x - 1) ? 1 : 0;
    }
    __syncthreads();

    // ---- last block finalizes ----
    if (s_last) {
        __threadfence();
        double s = 0.0; float c = 0.f;
        for (int i = tid; i < gridDim.x; i += TPB) {
            s += (double)g_psum[i];
            c += g_pcnt[i];
        }
#pragma unroll
        for (int off = 16; off > 0; off >>= 1) {
            s += __shfl_down_sync(0xffffffffu, s, off);
            c += __shfl_down_sync(0xffffffffu, c, off);
        }
        __shared__ double sds[4];
        __shared__ float  sdc[4];
        if (lane == 0) { sds[wid] = s; sdc[wid] = c; }
        __syncthreads();
        if (tid == 0) {
            double ts = sds[0] + sds[1] + sds[2] + sds[3];
            float  tc = sdc[0] + sdc[1] + sdc[2] + sdc[3];
            out[0] = (tc > 0.f) ? (float)(ts / (double)tc) : 0.f;
        }
    }
}

extern "C" void kernel_launch(void* const* d_in, const int* in_sizes, int n_in,
                              void* d_out, int out_size)
{
    const float* pred = (const float*)d_in[0];
    const float* gt   = (const float*)d_in[1];
    int B = in_sizes[0] / 24;          // [B, 8, 3] float32
    int nTiles = (B + TPB - 1) / TPB;
    int grid = nTiles < MAXG ? nTiles : MAXG;

    gsc_fused<<<grid, TPB>>>(pred, gt, (float*)d_out, B, nTiles);
}

// round 11
// speedup vs baseline: 1.2932x; 1.2932x over previous
#include <cuda_runtime.h>

#define EPS 1e-6f
#define TPB 256

// Scratch (no device allocation allowed). Zero-initialized at module load.
// Last block resets them after reading -> deterministic across graph replays.
__device__ double       g_sum;
__device__ unsigned int g_cnt;
__device__ unsigned int g_ticket;

__global__ void __launch_bounds__(TPB) gsc_fused(
    const float* __restrict__ pred, const float* __restrict__ gt,
    float* __restrict__ out, int B)
{
    const int tid = threadIdx.x;
    const int b   = blockIdx.x * TPB + tid;

    // ---- direct strided LDG.128 (R1 scheme: proven fastest load path) ----
    float pk[24], gk[24];
    if (b < B) {
        const float4* p4 = reinterpret_cast<const float4*>(pred) + (size_t)b * 6;
        const float4* g4 = reinterpret_cast<const float4*>(gt)   + (size_t)b * 6;
#pragma unroll
        for (int i = 0; i < 6; ++i) {
            float4 t = p4[i];
            pk[4*i+0] = t.x; pk[4*i+1] = t.y; pk[4*i+2] = t.z; pk[4*i+3] = t.w;
            float4 u = g4[i];
            gk[4*i+0] = u.x; gk[4*i+1] = u.y; gk[4*i+2] = u.z; gk[4*i+3] = u.w;
        }
    } else {
#pragma unroll
        for (int i = 0; i < 24; ++i) { pk[i] = 0.f; gk[i] = 0.f; }
    }

    // ---- stable "first 4 visible" select, fully unrolled (no spills) ----
    float px[4] = {0,0,0,0}, py[4] = {0,0,0,0};
    float gx[4] = {0,0,0,0}, gy[4] = {0,0,0,0};
    int nv = 0;
#pragma unroll
    for (int k = 0; k < 8; ++k) {
        bool vis = (pk[3*k+2] > 0.5f) && (gk[3*k+2] > 0.5f);
#pragma unroll
        for (int s = 0; s < 4; ++s) {
            if (vis && nv == s) {
                px[s] = pk[3*k+0]; py[s] = pk[3*k+1];
                gx[s] = gk[3*k+0]; gy[s] = gk[3*k+1];
            }
        }
        nv += vis ? 1 : 0;
    }
    bool valid = (b < B) && (nv >= 4);

    // ---- L_shape ----
    float d31x = px[2]-px[0], d31y = py[2]-py[0];
    float d42x = px[3]-px[1], d42y = py[3]-py[1];
    float e31x = gx[2]-gx[0], e31y = gy[2]-gy[0];
    float e42x = gx[3]-gx[1], e42y = gy[3]-gy[1];
    float pcr = __fdividef(sqrtf(d31x*d31x + d31y*d31y),
                           sqrtf(d42x*d42x + d42y*d42y) + EPS);
    float gcr = __fdividef(sqrtf(e31x*e31x + e31y*e31y),
                           sqrtf(e42x*e42x + e42y*e42y) + EPS);
    float L_shape = fabsf(pcr - gcr);

    // ---- L_edge ----
    float v12x = px[1]-px[0], v12y = py[1]-py[0];
    float v23x = px[2]-px[1], v23y = py[2]-py[1];
    float v34x = px[3]-px[2], v34y = py[3]-py[2];
    float v41x = px[0]-px[3], v41y = py[0]-py[3];
    float l12 = sqrtf(v12x*v12x + v12y*v12y);
    float l23 = sqrtf(v23x*v23x + v23y*v23y);
    float l34 = sqrtf(v34x*v34x + v34y*v34y);
    float l41 = sqrtf(v41x*v41x + v41y*v41y);
    float par1 = __fdividef(fabsf(l12 - l34), l12 + l34 + EPS);
    float par2 = __fdividef(fabsf(l23 - l41), l23 + l41 + EPS);
    float dot1 = fabsf(__fdividef(v12x*v41x + v12y*v41y, l12*l41 + EPS));
    float dot2 = fabsf(__fdividef(v12x*v23x + v12y*v23y, l12*l23 + EPS));
    float dot3 = fabsf(__fdividef(v23x*v34x + v23y*v34y, l23*l34 + EPS));
    float dot4 = fabsf(__fdividef(v34x*v41x + v34y*v41y, l34*l41 + EPS));
    float L_edge = 0.5f*(par1 + par2) + 0.25f*(dot1 + dot2 + dot3 + dot4);

    // ---- L_pos ----
    float dist = 0.f;
#pragma unroll
    for (int i = 0; i < 4; ++i) {
        float dx = px[i]-gx[i], dy = py[i]-gy[i];
        dist += sqrtf(dx*dx + dy*dy);
    }
    dist *= 0.25f;

    float d41x = px[3]-px[0], d41y = py[3]-py[0];
    float parea = 0.5f * (fabsf(v12x*d31y - v12y*d31x) +
                          fabsf(d31x*d41y - d31y*d41x));
    float w12x = gx[1]-gx[0], w12y = gy[1]-gy[0];
    float e41x = gx[3]-gx[0], e41y = gy[3]-gy[0];
    float garea = 0.5f * (fabsf(w12x*e31y - w12y*e31x) +
                          fabsf(e31x*e41y - e31y*e41x));
    float area_ratio = __fdividef(fabsf(parea - garea), garea + EPS);

    float dmx = 0.25f*((px[0]-gx[0]) + (px[1]-gx[1]) + (px[2]-gx[2]) + (px[3]-gx[3]));
    float dmy = 0.25f*((py[0]-gy[0]) + (py[1]-gy[1]) + (py[2]-gy[2]) + (py[3]-gy[3]));
    float rel = 0.f;
#pragma unroll
    for (int i = 0; i < 4; ++i) {
        float dx = (px[i]-gx[i]) - dmx;
        float dy = (py[i]-gy[i]) - dmy;
        rel += sqrtf(dx*dx + dy*dy);
    }
    rel *= 0.25f;

    float L_pos = 0.4f*dist + 0.3f*area_ratio + 0.3f*rel;
    float L     = 0.4f*L_shape + 0.3f*L_edge + 0.3f*L_pos;

    float contrib = valid ? L : 0.f;
    int   cnt     = valid ? 1 : 0;

    // ---- block reduction: warp shuffle -> smem -> one atomic per block ----
#pragma unroll
    for (int off = 16; off > 0; off >>= 1) {
        contrib += __shfl_down_sync(0xffffffffu, contrib, off);
        cnt     += __shfl_down_sync(0xffffffffu, cnt, off);
    }
    __shared__ float ssum[8];
    __shared__ int   scnt[8];
    __shared__ int   s_last;
    int lane = tid & 31;
    int wid  = tid >> 5;
    if (lane == 0) { ssum[wid] = contrib; scnt[wid] = cnt; }
    __syncthreads();
    if (tid == 0) {
        float s = 0.f; int c = 0;
#pragma unroll
        for (int i = 0; i < 8; ++i) { s += ssum[i]; c += scnt[i]; }
        atomicAdd(&g_sum, (double)s);
        atomicAdd(&g_cnt, (unsigned int)c);
        __threadfence();
        // wraps back to 0 after gridDim.x increments -> replay-safe
        unsigned int t = atomicInc(&g_ticket, gridDim.x - 1);
        s_last = (t == gridDim.x - 1) ? 1 : 0;
    }
    __syncthreads();

    // ---- last block finalizes and resets accumulators for next replay ----
    if (s_last && tid == 0) {
        __threadfence();
        double       ts = g_sum;
        unsigned int tc = g_cnt;
        out[0] = (tc > 0u) ? (float)(ts / (double)tc) : 0.f;
        g_sum = 0.0;
        g_cnt = 0u;
    }
}

extern "C" void kernel_launch(void* const* d_in, const int* in_sizes, int n_in,
                              void* d_out, int out_size)
{
    const float* pred = (const float*)d_in[0];
    const float* gt   = (const float*)d_in[1];
    int B = in_sizes[0] / 24;          // [B, 8, 3] float32
    int grid = (B + TPB - 1) / TPB;

    gsc_fused<<<grid, TPB>>>(pred, gt, (float*)d_out, B);
}

// round 12
// speedup vs baseline: 1.6901x; 1.3069x over previous
#include <cuda_runtime.h>

#define EPS 1e-6f
#define TPB 256

// Scratch (no device allocation allowed). Zero-initialized at module load.
// Last block resets accumulators after reading -> deterministic across replays.
__device__ double       g_sum;
__device__ unsigned int g_cnt;
__device__ unsigned int g_ticket;

__device__ __forceinline__ float fsqrt_fast(float x)
{
    float r;
    asm("sqrt.approx.f32 %0, %1;" : "=f"(r) : "f"(x));
    return r;
}

__global__ void __launch_bounds__(TPB, 5) gsc_fused(
    const float* __restrict__ pred, const float* __restrict__ gt,
    float* __restrict__ out, int B)
{
    const int tid = threadIdx.x;
    const int b   = blockIdx.x * TPB + tid;
    const bool inb = (b < B);

    // Select outputs (live across the whole kernel): 16 regs + nv.
    float px[4] = {0,0,0,0}, py[4] = {0,0,0,0};
    float gx[4] = {0,0,0,0}, gy[4] = {0,0,0,0};
    int nv = 0;

    // One keypoint's stable-select step, fully predicated (no dyn indexing).
#define SEL1(PX,PY,PZ,GX,GY,GZ)                                           \
    do {                                                                  \
        bool vis = ((PZ) > 0.5f) && ((GZ) > 0.5f);                        \
        if (vis && nv == 0) { px[0]=(PX); py[0]=(PY); gx[0]=(GX); gy[0]=(GY); } \
        if (vis && nv == 1) { px[1]=(PX); py[1]=(PY); gx[1]=(GX); gy[1]=(GY); } \
        if (vis && nv == 2) { px[2]=(PX); py[2]=(PY); gx[2]=(GX); gy[2]=(GY); } \
        if (vis && nv == 3) { px[3]=(PX); py[3]=(PY); gx[3]=(GX); gy[3]=(GY); } \
        nv += vis ? 1 : 0;                                                \
    } while (0)

    if (inb) {
        const float4* p4 = reinterpret_cast<const float4*>(pred) + (size_t)b * 6;
        const float4* g4 = reinterpret_cast<const float4*>(gt)   + (size_t)b * 6;

        // ---- half A: float4s 0..2 -> keypoints 0..3, then regs reused ----
        {
            float4 A0 = p4[0], A1 = p4[1], A2 = p4[2];
            float4 C0 = g4[0], C1 = g4[1], C2 = g4[2];
            SEL1(A0.x, A0.y, A0.z,  C0.x, C0.y, C0.z);   // k0
            SEL1(A0.w, A1.x, A1.y,  C0.w, C1.x, C1.y);   // k1
            SEL1(A1.z, A1.w, A2.x,  C1.z, C1.w, C2.x);   // k2
            SEL1(A2.y, A2.z, A2.w,  C2.y, C2.z, C2.w);   // k3
        }
        // ---- half B: float4s 3..5 -> keypoints 4..7 ----
        {
            float4 A0 = p4[3], A1 = p4[4], A2 = p4[5];
            float4 C0 = g4[3], C1 = g4[4], C2 = g4[5];
            SEL1(A0.x, A0.y, A0.z,  C0.x, C0.y, C0.z);   // k4
            SEL1(A0.w, A1.x, A1.y,  C0.w, C1.x, C1.y);   // k5
            SEL1(A1.z, A1.w, A2.x,  C1.z, C1.w, C2.x);   // k6
            SEL1(A2.y, A2.z, A2.w,  C2.y, C2.z, C2.w);   // k7
        }
    }
#undef SEL1
    bool valid = inb && (nv >= 4);

    // ---- L_shape ----
    float d31x = px[2]-px[0], d31y = py[2]-py[0];
    float d42x = px[3]-px[1], d42y = py[3]-py[1];
    float e31x = gx[2]-gx[0], e31y = gy[2]-gy[0];
    float e42x = gx[3]-gx[1], e42y = gy[3]-gy[1];
    float pcr = __fdividef(fsqrt_fast(d31x*d31x + d31y*d31y),
                           fsqrt_fast(d42x*d42x + d42y*d42y) + EPS);
    float gcr = __fdividef(fsqrt_fast(e31x*e31x + e31y*e31y),
                           fsqrt_fast(e42x*e42x + e42y*e42y) + EPS);
    float L_shape = fabsf(pcr - gcr);

    // ---- L_edge ----
    float v12x = px[1]-px[0], v12y = py[1]-py[0];
    float v23x = px[2]-px[1], v23y = py[2]-py[1];
    float v34x = px[3]-px[2], v34y = py[3]-py[2];
    float v41x = px[0]-px[3], v41y = py[0]-py[3];
    float l12 = fsqrt_fast(v12x*v12x + v12y*v12y);
    float l23 = fsqrt_fast(v23x*v23x + v23y*v23y);
    float l34 = fsqrt_fast(v34x*v34x + v34y*v34y);
    float l41 = fsqrt_fast(v41x*v41x + v41y*v41y);
    float par1 = __fdividef(fabsf(l12 - l34), l12 + l34 + EPS);
    float par2 = __fdividef(fabsf(l23 - l41), l23 + l41 + EPS);
    float dot1 = fabsf(__fdividef(v12x*v41x + v12y*v41y, l12*l41 + EPS));
    float dot2 = fabsf(__fdividef(v12x*v23x + v12y*v23y, l12*l23 + EPS));
    float dot3 = fabsf(__fdividef(v23x*v34x + v23y*v34y, l23*l34 + EPS));
    float dot4 = fabsf(__fdividef(v34x*v41x + v34y*v41y, l34*l41 + EPS));
    float L_edge = 0.5f*(par1 + par2) + 0.25f*(dot1 + dot2 + dot3 + dot4);

    // ---- L_pos ----
    float dist = 0.f;
#pragma unroll
    for (int i = 0; i < 4; ++i) {
        float dx = px[i]-gx[i], dy = py[i]-gy[i];
        dist += fsqrt_fast(dx*dx + dy*dy);
    }
    dist *= 0.25f;

    float d41x = px[3]-px[0], d41y = py[3]-py[0];
    float parea = 0.5f * (fabsf(v12x*d31y - v12y*d31x) +
                          fabsf(d31x*d41y - d31y*d41x));
    float w12x = gx[1]-gx[0], w12y = gy[1]-gy[0];
    float e41x = gx[3]-gx[0], e41y = gy[3]-gy[0];
    float garea = 0.5f * (fabsf(w12x*e31y - w12y*e31x) +
                          fabsf(e31x*e41y - e31y*e41x));
    float area_ratio = __fdividef(fabsf(parea - garea), garea + EPS);

    float dmx = 0.25f*((px[0]-gx[0]) + (px[1]-gx[1]) + (px[2]-gx[2]) + (px[3]-gx[3]));
    float dmy = 0.25f*((py[0]-gy[0]) + (py[1]-gy[1]) + (py[2]-gy[2]) + (py[3]-gy[3]));
    float rel = 0.f;
#pragma unroll
    for (int i = 0; i < 4; ++i) {
        float dx = (px[i]-gx[i]) - dmx;
        float dy = (py[i]-gy[i]) - dmy;
        rel += fsqrt_fast(dx*dx + dy*dy);
    }
    rel *= 0.25f;

    float L_pos = 0.4f*dist + 0.3f*area_ratio + 0.3f*rel;
    float L     = 0.4f*L_shape + 0.3f*L_edge + 0.3f*L_pos;

    float contrib = valid ? L : 0.f;

    // ---- warp reduction: shuffles for sum, ballot+popc for count ----
#pragma unroll
    for (int off = 16; off > 0; off >>= 1)
        contrib += __shfl_down_sync(0xffffffffu, contrib, off);
    unsigned int bal  = __ballot_sync(0xffffffffu, valid);
    int          wcnt = __popc(bal);

    __shared__ float ssum[8];
    __shared__ int   scnt[8];
    __shared__ int   s_last;
    int lane = tid & 31;
    int wid  = tid >> 5;
    if (lane == 0) { ssum[wid] = contrib; scnt[wid] = wcnt; }
    __syncthreads();
    if (tid == 0) {
        float s = 0.f; int c = 0;
#pragma unroll
        for (int i = 0; i < 8; ++i) { s += ssum[i]; c += scnt[i]; }
        atomicAdd(&g_sum, (double)s);
        atomicAdd(&g_cnt, (unsigned int)c);
        __threadfence();
        // wraps back to 0 after gridDim.x increments -> replay-safe
        unsigned int t = atomicInc(&g_ticket, gridDim.x - 1);
        s_last = (t == gridDim.x - 1) ? 1 : 0;
    }
    __syncthreads();

    // ---- last block finalizes and resets accumulators for next replay ----
    if (s_last && tid == 0) {
        __threadfence();
        double       ts = g_sum;
        unsigned int tc = g_cnt;
        out[0] = (tc > 0u) ? (float)(ts / (double)tc) : 0.f;
        g_sum = 0.0;
        g_cnt = 0u;
    }
}

extern "C" void kernel_launch(void* const* d_in, const int* in_sizes, int n_in,
                              void* d_out, int out_size)
{
    const float* pred = (const float*)d_in[0];
    const float* gt   = (const float*)d_in[1];
    int B = in_sizes[0] / 24;          // [B, 8, 3] float32
    int grid = (B + TPB - 1) / TPB;

    gsc_fused<<<grid, TPB>>>(pred, gt, (float*)d_out, B);
}